// round 3
// baseline (speedup 1.0000x reference)
#include <cuda_runtime.h>

#define EPSF 1e-9f

static constexpr int N = 4;              // n1 == n2 == 4
static constexpr int D = 4608;
static constexpr int D4 = D / 4;         // 1152 float4 per row
static constexpr int THREADS = 384;
static constexpr int GTH = 192;          // threads per i-group
static constexpr int ITERS = D4 / GTH;   // 6
static constexpr int NWARP = THREADS / 32;   // 12
static constexpr int GWARP = GTH / 32;       // 6 warps per group
static constexpr int LACC = 2 + 2 * N;       // 10 local accumulators per thread
static constexpr int NACC = N + N * N;       // 20 global accumulators

__global__ __launch_bounds__(THREADS, 4)
void negkl_kernel(const float4* __restrict__ in1, const float4* __restrict__ m1,
                  const float4* __restrict__ in2, const float4* __restrict__ m2,
                  float* __restrict__ out)
{
    const int b = blockIdx.x;
    const int t = threadIdx.x;
    const int grp = t / GTH;             // 0: p-rows {0,1}, 1: p-rows {2,3}
    const int g   = t % GTH;             // index within group
    const size_t base = (size_t)b * N * D4;

    // p rows owned by this group
    const float4* P  = in1 + base + (size_t)(2 * grp) * D4;
    const float4* M1 = m1  + base + (size_t)(2 * grp) * D4;
    // q rows: all 4, read by both groups (2nd reader hits L1)
    const float4* Q  = in2 + base;
    const float4* M2 = m2  + base;

    // ent[i_loc]       = sum_d p_i * log2(p_i + eps)
    // cross[i_loc][j]  = sum_d p_i * log2(q_j + eps)
    float ent[2];
    float cross[2][N];
    ent[0] = ent[1] = 0.f;
#pragma unroll
    for (int i = 0; i < 2; i++)
#pragma unroll
        for (int j = 0; j < N; j++) cross[i][j] = 0.f;

#pragma unroll
    for (int it = 0; it < ITERS; it++) {
        const int dc = it * GTH + g;

        // ---- p rows first (streaming, single reader) ----
        float4 p[2];
#pragma unroll
        for (int i = 0; i < 2; i++) {
            float4 v = __ldcs(&P[i * D4 + dc]);
            float4 m = __ldcs(&M1[i * D4 + dc]);
            p[i].x = v.x * m.x; p[i].y = v.y * m.y;
            p[i].z = v.z * m.z; p[i].w = v.w * m.w;
            float4 lp;
            lp.x = __log2f(p[i].x + EPSF);
            lp.y = __log2f(p[i].y + EPSF);
            lp.z = __log2f(p[i].z + EPSF);
            lp.w = __log2f(p[i].w + EPSF);
            ent[i] = fmaf(p[i].x, lp.x, fmaf(p[i].y, lp.y,
                     fmaf(p[i].z, lp.z, fmaf(p[i].w, lp.w, ent[i]))));
        }

        // ---- q rows: consume immediately, lq is a 4-reg transient ----
#pragma unroll
        for (int j = 0; j < N; j++) {
            float4 v = Q[j * D4 + dc];      // cached: 2nd group hits L1
            float4 m = M2[j * D4 + dc];
            float4 lq;
            lq.x = __log2f(fmaf(v.x, m.x, EPSF));
            lq.y = __log2f(fmaf(v.y, m.y, EPSF));
            lq.z = __log2f(fmaf(v.z, m.z, EPSF));
            lq.w = __log2f(fmaf(v.w, m.w, EPSF));
#pragma unroll
            for (int i = 0; i < 2; i++) {
                cross[i][j] = fmaf(p[i].x, lq.x, fmaf(p[i].y, lq.y,
                              fmaf(p[i].z, lq.z, fmaf(p[i].w, lq.w, cross[i][j]))));
            }
        }
    }

    // ---- block reduction ----
    // global accumulator layout in fin[]: ent[0..3], then cross[i*4+j]
    __shared__ float red[NACC][GWARP];
    __shared__ float fin[NACC];
    const int lane = t & 31;
    const int wid  = t >> 5;             // 0..11; warps 0-5 grp0, 6-11 grp1
    const int wig  = wid % GWARP;        // warp index within group

    float acc[LACC];
#pragma unroll
    for (int i = 0; i < 2; i++) acc[i] = ent[i];
#pragma unroll
    for (int i = 0; i < 2; i++)
#pragma unroll
        for (int j = 0; j < N; j++) acc[2 + i * N + j] = cross[i][j];

#pragma unroll
    for (int k = 0; k < LACC; k++) {
        float v = acc[k];
#pragma unroll
        for (int off = 16; off > 0; off >>= 1)
            v += __shfl_down_sync(0xffffffffu, v, off);
        if (lane == 0) {
            // map local k -> global accumulator index
            int gi = (k < 2) ? (grp * 2 + k)
                             : (N + (grp * 2 + (k - 2) / N) * N + (k - 2) % N);
            red[gi][wig] = v;
        }
    }
    __syncthreads();

    if (t < NACC) {
        float s = 0.f;
#pragma unroll
        for (int w = 0; w < GWARP; w++) s += red[t][w];
        fin[t] = s;
    }
    __syncthreads();

    if (t < N * N) {
        const int i = t >> 2;
        const float LN2 = 0.6931471805599453f;
        out[(size_t)b * (N * N) + t] = (fin[N + t] - fin[i]) * LN2;
    }
}

extern "C" void kernel_launch(void* const* d_in, const int* in_sizes, int n_in,
                              void* d_out, int out_size)
{
    const float4* in1 = (const float4*)d_in[0];
    const float4* m1  = (const float4*)d_in[1];
    const float4* in2 = (const float4*)d_in[2];
    const float4* m2  = (const float4*)d_in[3];
    float* out = (float*)d_out;

    const int bs = in_sizes[0] / (N * D);   // 2048
    negkl_kernel<<<bs, THREADS>>>(in1, m1, in2, m2, out);
}

// round 4
// speedup vs baseline: 1.0976x; 1.0976x over previous
#include <cuda_runtime.h>

#define EPSF 1e-9f

static constexpr int N = 4;              // n1 == n2 == 4
static constexpr int D = 4608;
static constexpr int D4 = D / 4;         // 1152 float4 per row
static constexpr int SPLIT = 2;          // d-range halves per batch
static constexpr int D4H = D4 / SPLIT;   // 576 float4 per half-row
static constexpr int THREADS = 192;
static constexpr int ITERS = D4H / THREADS;  // 3
static constexpr int NWARP = THREADS / 32;   // 6
static constexpr int NACC = N + N * N;       // 20 accumulators
static constexpr int BS_MAX = 2048;

// scratch[b][part][k], k: 0..3 ent, 4..19 cross[i*4+j]
__device__ float g_scratch[BS_MAX * SPLIT * NACC];

__global__ __launch_bounds__(THREADS, 6)
void negkl_partial_kernel(const float4* __restrict__ in1, const float4* __restrict__ m1,
                          const float4* __restrict__ in2, const float4* __restrict__ m2)
{
    const int c = blockIdx.x;
    const int b    = c >> 1;             // batch
    const int half = c & 1;              // d-range half
    const int t = threadIdx.x;
    const size_t base = (size_t)b * N * D4 + (size_t)half * D4H;
    const float4* P  = in1 + base;
    const float4* M1 = m1  + base;
    const float4* Q  = in2 + base;
    const float4* M2 = m2  + base;

    float ent[N];
    float cross[N][N];
#pragma unroll
    for (int i = 0; i < N; i++) {
        ent[i] = 0.f;
#pragma unroll
        for (int j = 0; j < N; j++) cross[i][j] = 0.f;
    }

#pragma unroll
    for (int it = 0; it < ITERS; it++) {
        const int dc = it * THREADS + t;

        // ---- q tile first: 8 batched streaming loads -> lq[4] ----
        float4 lq[N];
#pragma unroll
        for (int j = 0; j < N; j++) {
            float4 v = __ldcs(&Q[j * D4 + dc]);
            float4 m = __ldcs(&M2[j * D4 + dc]);
            lq[j].x = __log2f(fmaf(v.x, m.x, EPSF));
            lq[j].y = __log2f(fmaf(v.y, m.y, EPSF));
            lq[j].z = __log2f(fmaf(v.z, m.z, EPSF));
            lq[j].w = __log2f(fmaf(v.w, m.w, EPSF));
        }

        // ---- stream p rows, consume immediately ----
#pragma unroll
        for (int i = 0; i < N; i++) {
            float4 v = __ldcs(&P[i * D4 + dc]);
            float4 m = __ldcs(&M1[i * D4 + dc]);
            float4 p;
            p.x = v.x * m.x; p.y = v.y * m.y;
            p.z = v.z * m.z; p.w = v.w * m.w;

            float4 lp;
            lp.x = __log2f(p.x + EPSF);
            lp.y = __log2f(p.y + EPSF);
            lp.z = __log2f(p.z + EPSF);
            lp.w = __log2f(p.w + EPSF);
            ent[i] = fmaf(p.x, lp.x, fmaf(p.y, lp.y,
                     fmaf(p.z, lp.z, fmaf(p.w, lp.w, ent[i]))));

#pragma unroll
            for (int j = 0; j < N; j++) {
                cross[i][j] = fmaf(p.x, lq[j].x, fmaf(p.y, lq[j].y,
                              fmaf(p.z, lq[j].z, fmaf(p.w, lq[j].w, cross[i][j]))));
            }
        }
    }

    // ---- block reduction of 20 accumulators -> scratch ----
    __shared__ float red[NACC][NWARP];
    const int lane = t & 31;
    const int wid  = t >> 5;

    float acc[NACC];
#pragma unroll
    for (int i = 0; i < N; i++) acc[i] = ent[i];
#pragma unroll
    for (int i = 0; i < N; i++)
#pragma unroll
        for (int j = 0; j < N; j++) acc[N + i * N + j] = cross[i][j];

#pragma unroll
    for (int k = 0; k < NACC; k++) {
        float v = acc[k];
#pragma unroll
        for (int off = 16; off > 0; off >>= 1)
            v += __shfl_down_sync(0xffffffffu, v, off);
        if (lane == 0) red[k][wid] = v;
    }
    __syncthreads();

    if (t < NACC) {
        float s = 0.f;
#pragma unroll
        for (int w = 0; w < NWARP; w++) s += red[t][w];
        g_scratch[(size_t)c * NACC + t] = s;
    }
}

__global__ __launch_bounds__(256)
void negkl_combine_kernel(float* __restrict__ out, int total)
{
    const int idx = blockIdx.x * 256 + threadIdx.x;   // one per (b,i,j)
    if (idx >= total) return;
    const int b = idx >> 4;
    const int r = idx & 15;        // i*4+j
    const int i = r >> 2;
    const float* s = g_scratch + (size_t)b * SPLIT * NACC;
    const float ent   = s[i]     + s[NACC + i];
    const float cross = s[N + r] + s[NACC + N + r];
    const float LN2 = 0.6931471805599453f;
    out[idx] = (cross - ent) * LN2;
}

extern "C" void kernel_launch(void* const* d_in, const int* in_sizes, int n_in,
                              void* d_out, int out_size)
{
    const float4* in1 = (const float4*)d_in[0];
    const float4* m1  = (const float4*)d_in[1];
    const float4* in2 = (const float4*)d_in[2];
    const float4* m2  = (const float4*)d_in[3];
    float* out = (float*)d_out;

    const int bs = in_sizes[0] / (N * D);   // 2048
    negkl_partial_kernel<<<bs * SPLIT, THREADS>>>(in1, m1, in2, m2);
    const int total = bs * N * N;
    negkl_combine_kernel<<<(total + 255) / 256, 256>>>(out, total);
}